// round 10
// baseline (speedup 1.0000x reference)
#include <cuda_runtime.h>

#define BB  16
#define LL  128
#define LRR 128
#define VV  32000
#define NONE 0x7fffffff

// Scratch (no allocations allowed anywhere)
__device__ float    g_probs[BB * LL * LRR];   // [b][j][i] — probs[b,0,i,j] in ref notation
__device__ int      g_hard[BB * LL];          // argmax per (b,j)
__device__ float    g_colsum[BB * LL];        // per-(b,j) sum_i p[j][i]
__device__ float    g_partial[BB];            // per-batch weighted prob sum
__device__ unsigned g_fin = 0;                // k2 last-block counter (self-resetting)

// Labels-dtype detect: int64 LE => every odd 32-bit word is a zero high half.
__device__ __forceinline__ void detect_is64(const int* __restrict__ lab_raw,
                                            int t, int* s_is64) {
    if (t < 32) {
        int ok  = (lab_raw[2 * t + 1] == 0);
        int all = __all_sync(0xffffffffu, ok);
        if (t == 0) *s_is64 = all;
    }
}

// ===== k1: round-4 streaming kernel (proven ~5.7 TB/s) + colsum epilogue =====
// One block per (b,j): streaming reduce of 32000 logits -> (sumexp, argmax),
// gather 128 label probs, and NEW: reduce those probs -> g_colsum[row].
__global__ __launch_bounds__(256) void k1(const float* __restrict__ logits,
                                          const int* __restrict__ lab_raw) {
    const int row  = blockIdx.x;          // b*LL + j
    const int b    = row >> 7;
    const int t    = threadIdx.x;
    const int w    = t >> 5, lane = t & 31;
    const float* __restrict__ base = logits + (size_t)row * VV;

    __shared__ float s_s[8];
    __shared__ float s_v[8];
    __shared__ int   s_i[8];
    __shared__ int   s_lab[LRR];
    __shared__ float s_inv;
    __shared__ int   s_is64;

    detect_is64(lab_raw, t, &s_is64);
    __syncthreads();
    if (t < LRR) {
        s_lab[t] = s_is64 ? lab_raw[(b * LRR + t) * 2] : lab_raw[b * LRR + t];
    }

    float acc0 = 0.0f, acc1 = 0.0f;
    float vmax  = -3.0e38f;
    int   kbest = t;                       // winning quad index (exact elem found later)
    const float4* b4 = (const float4*)base;
    #pragma unroll 4
    for (int k = t; k < VV / 4; k += 256) {
        float4 v = __ldg(&b4[k]);
        acc0 += __expf(v.x) + __expf(v.y);   // MUFU.EX2 path
        acc1 += __expf(v.z) + __expf(v.w);
        float m = fmaxf(fmaxf(v.x, v.y), fmaxf(v.z, v.w));
        bool upd = m > vmax;               // strict > keeps earliest quad (first occurrence)
        kbest = upd ? k : kbest;
        vmax  = upd ? m : vmax;
    }
    float acc = acc0 + acc1;

    // Reconstruct exact element index once (quad reload hits L1)
    int imax;
    {
        float4 v = __ldg(&b4[kbest]);
        int i0 = kbest << 2;
        imax = (v.x == vmax) ? i0 : (v.y == vmax) ? i0 + 1
             : (v.z == vmax) ? i0 + 2 : i0 + 3;
    }

    // warp reduce: sum + (max, first-index) — tie -> smaller global index
    #pragma unroll
    for (int off = 16; off; off >>= 1) {
        acc += __shfl_down_sync(0xffffffffu, acc, off);
        float ov = __shfl_down_sync(0xffffffffu, vmax, off);
        int   oi = __shfl_down_sync(0xffffffffu, imax, off);
        if (ov > vmax || (ov == vmax && oi < imax)) { vmax = ov; imax = oi; }
    }
    if (lane == 0) { s_s[w] = acc; s_v[w] = vmax; s_i[w] = imax; }
    __syncthreads();
    if (t == 0) {
        float ts = s_s[0], tv = s_v[0];
        int   ti = s_i[0];
        #pragma unroll
        for (int q = 1; q < 8; q++) {
            ts += s_s[q];
            if (s_v[q] > tv || (s_v[q] == tv && s_i[q] < ti)) { tv = s_v[q]; ti = s_i[q]; }
        }
        s_inv = 1.0f / ts;
        g_hard[row] = ti;
    }
    __syncthreads();

    // Gather label probs + colsum reduce (probs are L1/L2 hits — row just streamed)
    float prob = 0.0f;
    if (t < LRR) {
        prob = __expf(__ldg(&base[s_lab[t]])) * s_inv;
        g_probs[row * LRR + t] = prob;     // probs[b,0,i=t,j], coalesced [b][j][i]
    }
    // block reduce of prob (top 128 threads contribute 0) -> g_colsum[row]
    #pragma unroll
    for (int off = 16; off; off >>= 1)
        prob += __shfl_down_sync(0xffffffffu, prob, off);
    if (lane == 0) s_s[w] = prob;
    __syncthreads();
    if (t == 0) {
        float cs = 0.0f;
        #pragma unroll
        for (int q = 0; q < 8; q++) cs += s_s[q];
        g_colsum[row] = cs;
    }
}

// ===== k2: featherweight — sudoku + closed-form total from colsums =====
// One block (128 threads) per batch.
//   total_b = 0.1*S_all + 0.4*(sum_{j unmCol} colsum[j] - corr) + 0.9*selSum
//   corr    = sum_{i matched} sum_{j unmCol} p[j][i]   (m = #matched ~ 0-2)
// Last block (ticket) computes loss = 1 - total/2048; counter self-resets.
__global__ __launch_bounds__(128) void k2(const int* __restrict__ lab_raw,
                                          float* __restrict__ out) {
    const int b = blockIdx.x;
    const int t = threadIdx.x;            // t = row index i (and column index j)

    __shared__ int           s_hard[LL];
    __shared__ int           s_fj[LRR];
    __shared__ int           s_colwin[LL];
    __shared__ unsigned char s_sel[LRR];
    __shared__ int           s_mlist[LRR];
    __shared__ int           s_m;
    __shared__ float         s_red[4];
    __shared__ int           s_is64;

    detect_is64(lab_raw, t, &s_is64);
    s_hard[t]   = g_hard[b * LL + t];
    s_colwin[t] = NONE;
    __syncthreads();
    const int lab = s_is64 ? lab_raw[(b * LRR + t) * 2] : lab_raw[b * LRR + t];

    // Row-first: thread t scans j ascending over broadcast s_hard[j]; keep first
    // match via predicated select (no serial dependence on memory, no atomics).
    int fj = NONE;
    #pragma unroll 8
    for (int j = 0; j < LL; j++) {
        bool hit = (s_hard[j] == lab) && (fj == NONE);
        fj = hit ? j : fj;
    }
    s_fj[t] = fj;
    __syncthreads();

    // Column dedup: winner of column fj is the smallest i
    if (fj != NONE) atomicMin(&s_colwin[fj], t);
    __syncthreads();
    const int sel = (fj != NONE && s_colwin[fj] == t);
    s_sel[t] = (unsigned char)sel;
    __syncthreads();

    // Deterministic matched-row list (thread 0 scans in fixed order)
    if (t == 0) {
        int m = 0;
        #pragma unroll 8
        for (int i = 0; i < LRR; i++)
            if (s_sel[i]) s_mlist[m++] = i;
        s_m = m;
    }
    __syncthreads();
    const int m = s_m;

    // Per-thread contributions (thread t plays both row i=t and column j=t):
    const float* __restrict__ pb = g_probs + b * LL * LRR;
    const float cs      = g_colsum[b * LL + t];          // colsum[j=t]
    const bool  colUnm  = (s_colwin[t] == NONE);
    float contrib = 0.1f * cs;                           // S_all term
    if (colUnm) contrib += 0.4f * cs;                    // unmatched-column term
    if (sel)    contrib += 0.9f * pb[fj * LRR + t];      // selected cell (row t)
    // correction: matched rows must not count in the both-unmatched term
    if (colUnm) {
        for (int q = 0; q < m; q++)                      // m ~ 0-2
            contrib -= 0.4f * pb[t * LRR + s_mlist[q]];  // p[j=t][i]
    }

    // Block reduce (4 warps, deterministic order)
    #pragma unroll
    for (int off = 16; off; off >>= 1)
        contrib += __shfl_down_sync(0xffffffffu, contrib, off);
    if ((t & 31) == 0) s_red[t >> 5] = contrib;
    __syncthreads();
    if (t == 0) {
        float s = s_red[0] + s_red[1] + s_red[2] + s_red[3];
        g_partial[b] = s;
        __threadfence();                   // release partial before ticket
        unsigned ticket = atomicAdd(&g_fin, 1u);
        if (ticket == BB - 1) {
            __threadfence();               // acquire all partials
            float tot = 0.0f;
            #pragma unroll
            for (int q = 0; q < BB; q++) tot += g_partial[q];
            out[0] = 1.0f - tot * (1.0f / 2048.0f);   // 1 + mean(-2*tot_b/256)
            g_fin = 0;                     // reset for next graph replay
        }
    }
}

extern "C" void kernel_launch(void* const* d_in, const int* in_sizes, int n_in,
                              void* d_out, int out_size) {
    // Resolve input order by element count (logits: 65.5M; labels: 2048/4096 words)
    int li = (in_sizes[0] > in_sizes[1]) ? 0 : 1;
    const float* logits = (const float*)d_in[li];
    const int*   labels = (const int*)d_in[1 - li];

    k1<<<BB * LL, 256>>>(logits, labels);
    k2<<<BB, 128>>>(labels, (float*)d_out);
}

// round 11
// speedup vs baseline: 1.2553x; 1.2553x over previous
#include <cuda_runtime.h>

#define BB  16
#define LL  128
#define LRR 128
#define VV  32000
#define NONE 0x7fffffff

// Scratch (no allocations allowed anywhere)
__device__ float    g_probs[BB * LL * LRR];   // [b][j][i] — probs[b,0,i,j] in ref notation
__device__ int      g_hard[BB * LL];          // argmax per (b,j)
__device__ float    g_partial[BB];            // per-batch weighted prob sum
__device__ unsigned g_fin = 0;                // k2 last-block counter (self-resetting)

// Labels-dtype detect: int64 LE => every odd 32-bit word is a zero high half.
__device__ __forceinline__ void detect_is64(const int* __restrict__ lab_raw,
                                            int t, int* s_is64) {
    if (t < 32) {
        int ok  = (lab_raw[2 * t + 1] == 0);
        int all = __all_sync(0xffffffffu, ok);
        if (t == 0) *s_is64 = all;
    }
}

// ===== k1: round-4 streaming kernel; ONLY change: __ldcs on the hot loop =====
// Logits are read-once (262MB through 126MB L2): evict-first streaming stops
// L2 thrash. One block per (b,j): (sumexp, argmax) + gather 128 label probs.
__global__ __launch_bounds__(256) void k1(const float* __restrict__ logits,
                                          const int* __restrict__ lab_raw) {
    const int row  = blockIdx.x;          // b*LL + j
    const int b    = row >> 7;
    const int t    = threadIdx.x;
    const int w    = t >> 5, lane = t & 31;
    const float* __restrict__ base = logits + (size_t)row * VV;

    __shared__ float s_s[8];
    __shared__ float s_v[8];
    __shared__ int   s_i[8];
    __shared__ int   s_lab[LRR];
    __shared__ float s_inv;
    __shared__ int   s_is64;

    detect_is64(lab_raw, t, &s_is64);
    __syncthreads();
    if (t < LRR) {
        s_lab[t] = s_is64 ? lab_raw[(b * LRR + t) * 2] : lab_raw[b * LRR + t];
    }

    float acc0 = 0.0f, acc1 = 0.0f;
    float vmax  = -3.0e38f;
    int   kbest = t;                       // winning quad index (exact elem found later)
    const float4* b4 = (const float4*)base;
    #pragma unroll 4
    for (int k = t; k < VV / 4; k += 256) {
        float4 v = __ldcs(&b4[k]);           // streaming load: evict-first in L2
        acc0 += __expf(v.x) + __expf(v.y);   // MUFU.EX2 path
        acc1 += __expf(v.z) + __expf(v.w);
        float m = fmaxf(fmaxf(v.x, v.y), fmaxf(v.z, v.w));
        bool upd = m > vmax;               // strict > keeps earliest quad (first occurrence)
        kbest = upd ? k : kbest;
        vmax  = upd ? m : vmax;
    }
    float acc = acc0 + acc1;

    // Reconstruct exact element index once
    int imax;
    {
        float4 v = __ldg(&b4[kbest]);
        int i0 = kbest << 2;
        imax = (v.x == vmax) ? i0 : (v.y == vmax) ? i0 + 1
             : (v.z == vmax) ? i0 + 2 : i0 + 3;
    }

    // warp reduce: sum + (max, first-index) — tie -> smaller global index
    #pragma unroll
    for (int off = 16; off; off >>= 1) {
        acc += __shfl_down_sync(0xffffffffu, acc, off);
        float ov = __shfl_down_sync(0xffffffffu, vmax, off);
        int   oi = __shfl_down_sync(0xffffffffu, imax, off);
        if (ov > vmax || (ov == vmax && oi < imax)) { vmax = ov; imax = oi; }
    }
    if (lane == 0) { s_s[w] = acc; s_v[w] = vmax; s_i[w] = imax; }
    __syncthreads();
    if (t == 0) {
        float ts = s_s[0], tv = s_v[0];
        int   ti = s_i[0];
        #pragma unroll
        for (int q = 1; q < 8; q++) {
            ts += s_s[q];
            if (s_v[q] > tv || (s_v[q] == tv && s_i[q] < ti)) { tv = s_v[q]; ti = s_i[q]; }
        }
        s_inv = 1.0f / ts;
        g_hard[row] = ti;
    }
    __syncthreads();
    if (t < LRR) {
        // probs[b,0,i=t,j] = exp(logit[label]) / sumexp ; coalesced store [b][j][i]
        g_probs[row * LRR + t] = __expf(__ldg(&base[s_lab[t]])) * s_inv;
    }
}

// ===== k2: round-4 version verbatim (measured best: 8.4us) =====
// One block per batch, 1024 threads. Sudoku via shared-mem atomicMin.
// Weights: 1.0 selected cell; 0.5 both-row-and-col unmatched; 0.1 otherwise.
// Last block finalizes: loss = 1 - total/2048.
__global__ __launch_bounds__(1024) void k2(const int* __restrict__ lab_raw,
                                           float* __restrict__ out) {
    const int b = blockIdx.x;
    const int t = threadIdx.x;

    __shared__ int           s_hard[LL];
    __shared__ int           s_lab[LRR];
    __shared__ int           s_fj[LRR];
    __shared__ int           s_colwin[LL];
    __shared__ unsigned char s_sel[LRR];
    __shared__ float         s_red[32];
    __shared__ int           s_is64;

    detect_is64(lab_raw, t, &s_is64);
    if (t < LL) {
        s_hard[t]   = g_hard[b * LL + t];
        s_fj[t]     = NONE;
        s_colwin[t] = NONE;
    }
    __syncthreads();
    if (t < LRR) {
        s_lab[t] = s_is64 ? lab_raw[(b * LRR + t) * 2] : lab_raw[b * LRR + t];
    }
    __syncthreads();

    // Row-first: scan 16384 (i,j) cells, 16 per thread. i fast (stride-1 LDS),
    // s_hard[j] broadcast. atomicMin keeps smallest j per row.
    #pragma unroll
    for (int c = 0; c < LL * LRR; c += 1024) {
        int cell = c + t;
        int i = cell & 127, j = cell >> 7;
        if (s_hard[j] == s_lab[i]) atomicMin(&s_fj[i], j);
    }
    __syncthreads();
    if (t < LRR) {
        int fj = s_fj[t];
        if (fj != NONE) atomicMin(&s_colwin[fj], t);   // column winner = min i
    }
    __syncthreads();
    if (t < LRR) {
        int fj = s_fj[t];
        s_sel[t] = (unsigned char)(fj != NONE && s_colwin[fj] == t);
    }
    __syncthreads();

    // Weighted sum over all cells (16 per thread, coalesced over g_probs [j][i])
    const float* __restrict__ pb = g_probs + b * LL * LRR;
    float acc = 0.0f;
    #pragma unroll
    for (int c = 0; c < LL * LRR; c += 1024) {
        int cell = c + t;
        int i = cell & 127, j = cell >> 7;
        float p = pb[cell];
        float wgt = 0.1f;
        if (s_sel[i] && s_fj[i] == j)              wgt = 1.0f;  // selected match
        else if (!s_sel[i] && s_colwin[j] == NONE) wgt = 0.5f;  // both unmatched
        acc += wgt * p;
    }

    // Block reduce (deterministic order)
    #pragma unroll
    for (int off = 16; off; off >>= 1)
        acc += __shfl_down_sync(0xffffffffu, acc, off);
    if ((t & 31) == 0) s_red[t >> 5] = acc;
    __syncthreads();
    if (t == 0) {
        float s = 0.0f;
        #pragma unroll
        for (int q = 0; q < 32; q++) s += s_red[q];
        g_partial[b] = s;
        __threadfence();                   // release partial before ticket
        unsigned ticket = atomicAdd(&g_fin, 1u);
        if (ticket == BB - 1) {
            __threadfence();               // acquire all partials
            float tot = 0.0f;
            #pragma unroll
            for (int q = 0; q < BB; q++) tot += g_partial[q];
            out[0] = 1.0f - tot * (1.0f / 2048.0f);
            g_fin = 0;                     // reset for next graph replay
        }
    }
}

extern "C" void kernel_launch(void* const* d_in, const int* in_sizes, int n_in,
                              void* d_out, int out_size) {
    // Resolve input order by element count (logits: 65.5M; labels: 2048/4096 words)
    int li = (in_sizes[0] > in_sizes[1]) ? 0 : 1;
    const float* logits = (const float*)d_in[li];
    const int*   labels = (const int*)d_in[1 - li];

    k1<<<BB * LL, 256>>>(logits, labels);
    k2<<<BB, 1024>>>(labels, (float*)d_out);
}